// round 15
// baseline (speedup 1.0000x reference)
#include <cuda_runtime.h>
#include <cstdint>

// Problem constants
#define Bc 64
#define Sc 512
#define Wc 384
#define Dc 768
#define Tc 21

// Scratch (no cudaMalloc allowed)
__device__ float g_em[Bc * Wc * Tc];   // emissions (B, W, T)
__device__ float g_llh[Bc];            // per-batch (log_z - num)

__device__ __forceinline__ void ffma2(unsigned long long &d,
                                      unsigned long long a,
                                      unsigned long long b) {
    asm("fma.rn.f32x2 %0, %1, %2, %0;" : "+l"(d) : "l"(a), "l"(b));
}

// ---------------------------------------------------------------------------
// Kernel 1: emissions[b,w,t] = dot(hidden[b, word_maps[b,w], :], W_tag[t,:]) + b_tag[t]
// One warp handles 4 rows (b,w). Feats held in registers as f32x2 pairs,
// W_tag streamed from L1. Packed fma.rn.f32x2 halves FMA issue.
// ---------------------------------------------------------------------------
__global__ void __launch_bounds__(256)
emissions_kernel(const float* __restrict__ hidden,
                 const float* __restrict__ W_tag,
                 const float* __restrict__ b_tag,
                 const int*   __restrict__ word_maps)
{
    const int warp = (blockIdx.x * blockDim.x + threadIdx.x) >> 5;
    const int lane = threadIdx.x & 31;
    const int r0 = warp * 4;
    if (r0 >= Bc * Wc) return;

    // Load 4 feature rows into registers: 6 x 16B per lane per row.
    ulonglong2 f[4][6];
#pragma unroll
    for (int j = 0; j < 4; j++) {
        const int row = r0 + j;
        const int b = row / Wc;
        const int pos = word_maps[row];
        const ulonglong2* p = reinterpret_cast<const ulonglong2*>(
            hidden + ((size_t)(b * Sc + pos)) * Dc);
#pragma unroll
        for (int k = 0; k < 6; k++) f[j][k] = p[lane + 32 * k];
    }

    const ulonglong2* WT = reinterpret_cast<const ulonglong2*>(W_tag);

#pragma unroll 1
    for (int t = 0; t < Tc; t++) {
        unsigned long long acc0 = 0ull, acc1 = 0ull, acc2 = 0ull, acc3 = 0ull;
#pragma unroll
        for (int k = 0; k < 6; k++) {
            ulonglong2 w2 = WT[t * 192 + lane + 32 * k];
            ffma2(acc0, f[0][k].x, w2.x); ffma2(acc0, f[0][k].y, w2.y);
            ffma2(acc1, f[1][k].x, w2.x); ffma2(acc1, f[1][k].y, w2.y);
            ffma2(acc2, f[2][k].x, w2.x); ffma2(acc2, f[2][k].y, w2.y);
            ffma2(acc3, f[3][k].x, w2.x); ffma2(acc3, f[3][k].y, w2.y);
        }
        const float bt = b_tag[t];
        unsigned long long accs[4] = {acc0, acc1, acc2, acc3};
#pragma unroll
        for (int j = 0; j < 4; j++) {
            float lo = __uint_as_float((unsigned)(accs[j] & 0xffffffffull));
            float hi = __uint_as_float((unsigned)(accs[j] >> 32));
            float s = lo + hi;
#pragma unroll
            for (int o = 16; o > 0; o >>= 1)
                s += __shfl_xor_sync(0xffffffffu, s, o);
            if (lane == 0)
                g_em[(size_t)(r0 + j) * Tc + t] = s + bt;
        }
    }
}

// ---------------------------------------------------------------------------
// Kernel 2: per-batch CRF. Block = 128 threads, one block per batch.
//   - all threads preload emissions (32 KB), tags, mask (int32!), trans into smem
//   - warp 0 runs the 383-step forward scan in the PROBABILITY domain
//     (scaled forward algorithm: exp(trans) precomputed in registers,
//      1 EX2/lane/step, renormalize every 8 steps)
//   - warps 1-3 compute the numerator in parallel
// ---------------------------------------------------------------------------
__global__ void __launch_bounds__(128)
crf_kernel(const float* __restrict__ start_trans,
           const float* __restrict__ end_trans,
           const float* __restrict__ trans,
           const int*   __restrict__ tags,
           const int*   __restrict__ word_mask)   // int32: nonzero == true
{
    __shared__ __align__(16) float em_s[Wc * Tc];   // 8064 floats = 32.25 KB
    __shared__ int tags_s[Wc];
    __shared__ int mask_s[Wc];
    __shared__ float trans_s[Tc * Tc];
    __shared__ float rsum[4];
    __shared__ int   rcnt[4];
    __shared__ float logz_sh;

    const int b = blockIdx.x;
    const int tid = threadIdx.x;

    // ---- cooperative preload ----
    {
        const float4* src = reinterpret_cast<const float4*>(g_em + (size_t)b * Wc * Tc);
        float4* dst = reinterpret_cast<float4*>(em_s);
        for (int i = tid; i < (Wc * Tc) / 4; i += 128) dst[i] = src[i];
        for (int i = tid; i < Wc; i += 128) {
            tags_s[i] = tags[b * Wc + i];
            mask_s[i] = (word_mask[b * Wc + i] != 0);
        }
        for (int i = tid; i < Tc * Tc; i += 128) trans_s[i] = trans[i];
    }
    __syncthreads();

    if (tid >= 32) {
        // ---- numerator (warps 1-3, 96 threads) ----
        const int t0 = tid - 32;
        float local = 0.f;
        int cnt = 0;
        for (int w = t0; w < Wc; w += 96) {
            const int m = mask_s[w];
            cnt += m;
            if (w >= 1 && m) {
                const int tp = tags_s[w - 1];
                const int tc = tags_s[w];
                local += trans_s[tp * Tc + tc] + em_s[w * Tc + tc];
            }
        }
#pragma unroll
        for (int o = 16; o > 0; o >>= 1) {
            local += __shfl_xor_sync(0xffffffffu, local, o);
            cnt   += __shfl_xor_sync(0xffffffffu, cnt, o);
        }
        if ((tid & 31) == 0) { rsum[tid >> 5] = local; rcnt[tid >> 5] = cnt; }
    } else {
        // ---- forward scan (warp 0) ----
        const int lane = tid;
        const int lc = (lane < Tc) ? lane : 0;
        const float LOG2E = 1.44269504088896340736f;

        // E[t][lane] = exp(trans[t, lane]) held in registers (column per lane)
        float Ecol[Tc];
#pragma unroll
        for (int t = 0; t < Tc; t++)
            Ecol[t] = exp2f(trans_s[t * Tc + lc] * LOG2E);

        float a;
        {
            const float sc0 = start_trans[lc] + em_s[lc];
            a = (lane < Tc) ? exp2f(sc0 * LOG2E) : 0.f;
        }
        float logZ = 0.f;

#pragma unroll 4
        for (int w = 1; w < Wc; ++w) {
            const float eem = exp2f(em_s[w * Tc + lc] * LOG2E);
            if (mask_s[w]) {
                float a0 = 0.f, a1 = 0.f, a2 = 0.f;
#pragma unroll
                for (int t = 0; t < Tc; t += 3) {
                    float v0 = __shfl_sync(0xffffffffu, a, t);
                    a0 = fmaf(v0, Ecol[t], a0);
                    if (t + 1 < Tc) {
                        float v1 = __shfl_sync(0xffffffffu, a, t + 1);
                        a1 = fmaf(v1, Ecol[t + 1], a1);
                    }
                    if (t + 2 < Tc) {
                        float v2 = __shfl_sync(0xffffffffu, a, t + 2);
                        a2 = fmaf(v2, Ecol[t + 2], a2);
                    }
                }
                a = (lane < Tc) ? (a0 + a1 + a2) * eem : 0.f;
            }
            if ((w & 7) == 0) {
                // renormalize: logZ += log(sum a); a /= sum
                float s = a;
#pragma unroll
                for (int o = 16; o > 0; o >>= 1)
                    s += __shfl_xor_sync(0xffffffffu, s, o);
                logZ += __logf(s);
                a *= __fdividef(1.0f, s);
            }
        }

        float fin = (lane < Tc) ? a * exp2f(end_trans[lc] * LOG2E) : 0.f;
        float s = fin;
#pragma unroll
        for (int o = 16; o > 0; o >>= 1)
            s += __shfl_xor_sync(0xffffffffu, s, o);
        if (lane == 0) logz_sh = logZ + __logf(s);
    }
    __syncthreads();

    if (tid == 0) {
        float num = rsum[1] + rsum[2] + rsum[3];
        const int len = rcnt[1] + rcnt[2] + rcnt[3];
        const int tag0 = tags_s[0];
        num += start_trans[tag0] + em_s[tag0];
        num += end_trans[tags_s[len - 1]];
        g_llh[b] = logz_sh - num;   // = -(llh_b)
    }
}

// ---------------------------------------------------------------------------
// Kernel 3: out = mean over batches of (log_z - num)  (= -mean llh)
// ---------------------------------------------------------------------------
__global__ void finalize_kernel(float* __restrict__ out)
{
    const int lane = threadIdx.x;
    float v = g_llh[lane] + g_llh[lane + 32];
#pragma unroll
    for (int o = 16; o > 0; o >>= 1)
        v += __shfl_xor_sync(0xffffffffu, v, o);
    if (lane == 0) out[0] = v * (1.0f / 64.0f);
}

// ---------------------------------------------------------------------------
extern "C" void kernel_launch(void* const* d_in, const int* in_sizes, int n_in,
                              void* d_out, int out_size)
{
    const float* hidden      = (const float*)d_in[0];
    const float* W_tag       = (const float*)d_in[1];
    const float* b_tag       = (const float*)d_in[2];
    const float* start_trans = (const float*)d_in[3];
    const float* end_trans   = (const float*)d_in[4];
    const float* trans       = (const float*)d_in[5];
    const int*   word_maps   = (const int*)d_in[6];
    const int*   tags        = (const int*)d_in[7];
    const int*   word_mask   = (const int*)d_in[8];

    // 24576 rows / 4 rows per warp / 8 warps per block = 768 blocks
    emissions_kernel<<<768, 256>>>(hidden, W_tag, b_tag, word_maps);
    crf_kernel<<<Bc, 128>>>(start_trans, end_trans, trans, tags, word_mask);
    finalize_kernel<<<1, 32>>>((float*)d_out);
}

// round 16
// speedup vs baseline: 1.0037x; 1.0037x over previous
#include <cuda_runtime.h>
#include <cstdint>

// Problem constants
#define Bc 64
#define Sc 512
#define Wc 384
#define Dc 768
#define Tc 21

// Scratch (no cudaMalloc allowed)
__device__ float g_em[Bc * Wc * Tc];   // emissions (B, W, T)
__device__ float g_llh[Bc];            // per-batch (log_z - num)

__device__ __forceinline__ void ffma2(unsigned long long &d,
                                      unsigned long long a,
                                      unsigned long long b) {
    asm("fma.rn.f32x2 %0, %1, %2, %0;" : "+l"(d) : "l"(a), "l"(b));
}

// ---------------------------------------------------------------------------
// Kernel 1: emissions[b,w,t] = dot(hidden[b, word_maps[b,w], :], W_tag[t,:]) + b_tag[t]
// One warp handles 4 rows (b,w). Feats held in registers as f32x2 pairs,
// W_tag streamed from L1. Packed fma.rn.f32x2 halves FMA issue.
// ---------------------------------------------------------------------------
__global__ void __launch_bounds__(256)
emissions_kernel(const float* __restrict__ hidden,
                 const float* __restrict__ W_tag,
                 const float* __restrict__ b_tag,
                 const int*   __restrict__ word_maps)
{
    const int warp = (blockIdx.x * blockDim.x + threadIdx.x) >> 5;
    const int lane = threadIdx.x & 31;
    const int r0 = warp * 4;
    if (r0 >= Bc * Wc) return;

    // Load 4 feature rows into registers: 6 x 16B per lane per row.
    ulonglong2 f[4][6];
#pragma unroll
    for (int j = 0; j < 4; j++) {
        const int row = r0 + j;
        const int b = row / Wc;
        const int pos = word_maps[row];
        const ulonglong2* p = reinterpret_cast<const ulonglong2*>(
            hidden + ((size_t)(b * Sc + pos)) * Dc);
#pragma unroll
        for (int k = 0; k < 6; k++) f[j][k] = p[lane + 32 * k];
    }

    const ulonglong2* WT = reinterpret_cast<const ulonglong2*>(W_tag);

#pragma unroll 1
    for (int t = 0; t < Tc; t++) {
        unsigned long long acc0 = 0ull, acc1 = 0ull, acc2 = 0ull, acc3 = 0ull;
#pragma unroll
        for (int k = 0; k < 6; k++) {
            ulonglong2 w2 = WT[t * 192 + lane + 32 * k];
            ffma2(acc0, f[0][k].x, w2.x); ffma2(acc0, f[0][k].y, w2.y);
            ffma2(acc1, f[1][k].x, w2.x); ffma2(acc1, f[1][k].y, w2.y);
            ffma2(acc2, f[2][k].x, w2.x); ffma2(acc2, f[2][k].y, w2.y);
            ffma2(acc3, f[3][k].x, w2.x); ffma2(acc3, f[3][k].y, w2.y);
        }
        const float bt = b_tag[t];
        unsigned long long accs[4] = {acc0, acc1, acc2, acc3};
#pragma unroll
        for (int j = 0; j < 4; j++) {
            float lo = __uint_as_float((unsigned)(accs[j] & 0xffffffffull));
            float hi = __uint_as_float((unsigned)(accs[j] >> 32));
            float s = lo + hi;
#pragma unroll
            for (int o = 16; o > 0; o >>= 1)
                s += __shfl_xor_sync(0xffffffffu, s, o);
            if (lane == 0)
                g_em[(size_t)(r0 + j) * Tc + t] = s + bt;
        }
    }
}

// ---------------------------------------------------------------------------
// Kernel 2: per-batch CRF. Block = 128 threads, one block per batch.
//   - all threads preload emissions (32 KB), tags, mask (int32!), trans into smem
//   - warp 0 runs the 383-step forward scan in the PROBABILITY domain
//     (scaled forward algorithm: exp(trans) precomputed in registers,
//      1 EX2/lane/step, renormalize every 8 steps)
//   - warps 1-3 compute the numerator in parallel
// ---------------------------------------------------------------------------
__global__ void __launch_bounds__(128)
crf_kernel(const float* __restrict__ start_trans,
           const float* __restrict__ end_trans,
           const float* __restrict__ trans,
           const int*   __restrict__ tags,
           const int*   __restrict__ word_mask)   // int32: nonzero == true
{
    __shared__ __align__(16) float em_s[Wc * Tc];   // 8064 floats = 32.25 KB
    __shared__ int tags_s[Wc];
    __shared__ int mask_s[Wc];
    __shared__ float trans_s[Tc * Tc];
    __shared__ float rsum[4];
    __shared__ int   rcnt[4];
    __shared__ float logz_sh;

    const int b = blockIdx.x;
    const int tid = threadIdx.x;

    // ---- cooperative preload ----
    {
        const float4* src = reinterpret_cast<const float4*>(g_em + (size_t)b * Wc * Tc);
        float4* dst = reinterpret_cast<float4*>(em_s);
        for (int i = tid; i < (Wc * Tc) / 4; i += 128) dst[i] = src[i];
        for (int i = tid; i < Wc; i += 128) {
            tags_s[i] = tags[b * Wc + i];
            mask_s[i] = (word_mask[b * Wc + i] != 0);
        }
        for (int i = tid; i < Tc * Tc; i += 128) trans_s[i] = trans[i];
    }
    __syncthreads();

    if (tid >= 32) {
        // ---- numerator (warps 1-3, 96 threads) ----
        const int t0 = tid - 32;
        float local = 0.f;
        int cnt = 0;
        for (int w = t0; w < Wc; w += 96) {
            const int m = mask_s[w];
            cnt += m;
            if (w >= 1 && m) {
                const int tp = tags_s[w - 1];
                const int tc = tags_s[w];
                local += trans_s[tp * Tc + tc] + em_s[w * Tc + tc];
            }
        }
#pragma unroll
        for (int o = 16; o > 0; o >>= 1) {
            local += __shfl_xor_sync(0xffffffffu, local, o);
            cnt   += __shfl_xor_sync(0xffffffffu, cnt, o);
        }
        if ((tid & 31) == 0) { rsum[tid >> 5] = local; rcnt[tid >> 5] = cnt; }
    } else {
        // ---- forward scan (warp 0) ----
        const int lane = tid;
        const int lc = (lane < Tc) ? lane : 0;
        const float LOG2E = 1.44269504088896340736f;

        // E[t][lane] = exp(trans[t, lane]) held in registers (column per lane)
        float Ecol[Tc];
#pragma unroll
        for (int t = 0; t < Tc; t++)
            Ecol[t] = exp2f(trans_s[t * Tc + lc] * LOG2E);

        float a;
        {
            const float sc0 = start_trans[lc] + em_s[lc];
            a = (lane < Tc) ? exp2f(sc0 * LOG2E) : 0.f;
        }
        float logZ = 0.f;

#pragma unroll 4
        for (int w = 1; w < Wc; ++w) {
            const float eem = exp2f(em_s[w * Tc + lc] * LOG2E);
            if (mask_s[w]) {
                float a0 = 0.f, a1 = 0.f, a2 = 0.f;
#pragma unroll
                for (int t = 0; t < Tc; t += 3) {
                    float v0 = __shfl_sync(0xffffffffu, a, t);
                    a0 = fmaf(v0, Ecol[t], a0);
                    if (t + 1 < Tc) {
                        float v1 = __shfl_sync(0xffffffffu, a, t + 1);
                        a1 = fmaf(v1, Ecol[t + 1], a1);
                    }
                    if (t + 2 < Tc) {
                        float v2 = __shfl_sync(0xffffffffu, a, t + 2);
                        a2 = fmaf(v2, Ecol[t + 2], a2);
                    }
                }
                a = (lane < Tc) ? (a0 + a1 + a2) * eem : 0.f;
            }
            if ((w & 7) == 0) {
                // renormalize: logZ += log(sum a); a /= sum
                float s = a;
#pragma unroll
                for (int o = 16; o > 0; o >>= 1)
                    s += __shfl_xor_sync(0xffffffffu, s, o);
                logZ += __logf(s);
                a *= __fdividef(1.0f, s);
            }
        }

        float fin = (lane < Tc) ? a * exp2f(end_trans[lc] * LOG2E) : 0.f;
        float s = fin;
#pragma unroll
        for (int o = 16; o > 0; o >>= 1)
            s += __shfl_xor_sync(0xffffffffu, s, o);
        if (lane == 0) logz_sh = logZ + __logf(s);
    }
    __syncthreads();

    if (tid == 0) {
        float num = rsum[1] + rsum[2] + rsum[3];
        const int len = rcnt[1] + rcnt[2] + rcnt[3];
        const int tag0 = tags_s[0];
        num += start_trans[tag0] + em_s[tag0];
        num += end_trans[tags_s[len - 1]];
        g_llh[b] = logz_sh - num;   // = -(llh_b)
    }
}

// ---------------------------------------------------------------------------
// Kernel 3: out = mean over batches of (log_z - num)  (= -mean llh)
// ---------------------------------------------------------------------------
__global__ void finalize_kernel(float* __restrict__ out)
{
    const int lane = threadIdx.x;
    float v = g_llh[lane] + g_llh[lane + 32];
#pragma unroll
    for (int o = 16; o > 0; o >>= 1)
        v += __shfl_xor_sync(0xffffffffu, v, o);
    if (lane == 0) out[0] = v * (1.0f / 64.0f);
}

// ---------------------------------------------------------------------------
extern "C" void kernel_launch(void* const* d_in, const int* in_sizes, int n_in,
                              void* d_out, int out_size)
{
    const float* hidden      = (const float*)d_in[0];
    const float* W_tag       = (const float*)d_in[1];
    const float* b_tag       = (const float*)d_in[2];
    const float* start_trans = (const float*)d_in[3];
    const float* end_trans   = (const float*)d_in[4];
    const float* trans       = (const float*)d_in[5];
    const int*   word_maps   = (const int*)d_in[6];
    const int*   tags        = (const int*)d_in[7];
    const int*   word_mask   = (const int*)d_in[8];

    // 24576 rows / 4 rows per warp / 8 warps per block = 768 blocks
    emissions_kernel<<<768, 256>>>(hidden, W_tag, b_tag, word_maps);
    crf_kernel<<<Bc, 128>>>(start_trans, end_trans, trans, tags, word_mask);
    finalize_kernel<<<1, 32>>>((float*)d_out);
}